// round 12
// baseline (speedup 1.0000x reference)
#include <cuda_runtime.h>
#include <float.h>
#include <math.h>

// Problem geometry
#define HH 512
#define WW 512
#define SLICES 128                 // B*P = 64*2
#define NB 32                      // blocks per slice
#define TPB 256                    // threads per block
#define NBLOCKS (SLICES*NB)        // 4096
#define ELEMS_PER_SLICE (HH*WW)    // 262144
#define ELEMS_PER_BLOCK (ELEMS_PER_SLICE/NB)   // 8192
#define VEC4_PER_BLOCK  (ELEMS_PER_BLOCK/4)    // 2048
#define VEC4_PER_THREAD (VEC4_PER_BLOCK/TPB)   // 8

// Per-block partials (static device scratch; 16B-aligned for float4 loads)
__device__ __align__(16) float g_s [NBLOCKS];
__device__ __align__(16) float g_sx[NBLOCKS];
__device__ __align__(16) float g_sy[NBLOCKS];
__device__ __align__(16) float g_tv[NBLOCKS];
__device__ __align__(16) int   g_ti[NBLOCKS];
__device__ unsigned int g_count;   // zero at load; winner resets each run

__global__ __launch_bounds__(TPB)
void dsnt_fused(const float4* __restrict__ inp, const float4* __restrict__ tgt,
                float* __restrict__ out)
{
    const int blk   = blockIdx.x;          // 0..NBLOCKS-1
    const int slice = blk >> 5;            // /NB
    const int sub   = blk & (NB-1);
    const int tid   = threadIdx.x;
    const int wid   = tid >> 5;
    const int lid   = tid & 31;

    const int slice_base4 = slice * (ELEMS_PER_SLICE/4);
    const int chunk_base4 = sub * VEC4_PER_BLOCK;

    float s = 0.f, sx = 0.f, sy = 0.f;
    float tv = -FLT_MAX;
    int   ti = 0x7fffffff;

#pragma unroll
    for (int k = 0; k < VEC4_PER_THREAD; k++) {
        const int local4 = k * TPB + tid;               // block-stride, coalesced
        const int g4     = slice_base4 + chunk_base4 + local4;
        const float4 v = inp[g4];
        const float4 t = tgt[g4];

        const int ei  = (chunk_base4 + local4) << 2;    // element index in slice
        const int row = ei >> 9;                        // /512
        const int col = ei & 511;

        const float e0 = __expf(v.x);
        const float e1 = __expf(v.y);
        const float e2 = __expf(v.z);
        const float e3 = __expf(v.w);
        const float es = (e0 + e1) + (e2 + e3);
        s  += es;
        sx += e0*(float)(col+1) + e1*(float)(col+2)
            + e2*(float)(col+3) + e3*(float)(col+4);
        sy += es * (float)(row+1);

        // target running argmax (indices visited in increasing order per thread)
        if (t.x > tv) { tv = t.x; ti = ei;     }
        if (t.y > tv) { tv = t.y; ti = ei + 1; }
        if (t.z > tv) { tv = t.z; ti = ei + 2; }
        if (t.w > tv) { tv = t.w; ti = ei + 3; }
    }

    // ---- warp reduce ----
#pragma unroll
    for (int off = 16; off > 0; off >>= 1) {
        s  += __shfl_down_sync(0xffffffffu, s,  off);
        sx += __shfl_down_sync(0xffffffffu, sx, off);
        sy += __shfl_down_sync(0xffffffffu, sy, off);
        float ov = __shfl_down_sync(0xffffffffu, tv, off);
        int   oi = __shfl_down_sync(0xffffffffu, ti, off);
        if (ov > tv || (ov == tv && oi < ti)) { tv = ov; ti = oi; }
    }

    __shared__ float sh_s[8], sh_sx[8], sh_sy[8], sh_tv[8];
    __shared__ int   sh_ti[8];
    __shared__ int   amLast;
    if (lid == 0) { sh_s[wid]=s; sh_sx[wid]=sx; sh_sy[wid]=sy; sh_tv[wid]=tv; sh_ti[wid]=ti; }
    if (tid == 0) amLast = 0;
    __syncthreads();

    if (wid == 0) {
        s  = (lid < 8) ? sh_s [lid] : 0.f;
        sx = (lid < 8) ? sh_sx[lid] : 0.f;
        sy = (lid < 8) ? sh_sy[lid] : 0.f;
        tv = (lid < 8) ? sh_tv[lid] : -FLT_MAX;
        ti = (lid < 8) ? sh_ti[lid] : 0x7fffffff;
#pragma unroll
        for (int off = 4; off > 0; off >>= 1) {
            s  += __shfl_down_sync(0xffffffffu, s,  off);
            sx += __shfl_down_sync(0xffffffffu, sx, off);
            sy += __shfl_down_sync(0xffffffffu, sy, off);
            float ov = __shfl_down_sync(0xffffffffu, tv, off);
            int   oi = __shfl_down_sync(0xffffffffu, ti, off);
            if (ov > tv || (ov == tv && oi < ti)) { tv = ov; ti = oi; }
        }
        if (lid == 0) {
            g_s [blk] = s;
            g_sx[blk] = sx;
            g_sy[blk] = sy;
            g_tv[blk] = tv;
            g_ti[blk] = ti;

            // Release-atomic ticket: orders THIS thread's partial stores into
            // L2 before the increment. One L2 op per block — no membar.gpu,
            // no L1 flush (the R3 poison).
            unsigned int old;
            asm volatile("atom.add.release.gpu.global.u32 %0, [%1], 1;"
                         : "=r"(old) : "l"(&g_count) : "memory");
            if (old == NBLOCKS - 1u) amLast = 1;
        }
    }
    __syncthreads();
    if (!amLast) return;

    // =====================================================================
    // Winner block: all 4096 partial sets are in L2 (released before their
    // tickets, and our acquire-free reads use __ldcg = L1-bypass, L2-coherent).
    // 256 threads, 2 per slice, 16 partials each via float4 loads (MLP=20).
    // =====================================================================
    __shared__ float sS [TPB], sSX[TPB], sSY[TPB], sMV[TPB];
    __shared__ int   sMI[TPB];
    __shared__ float sh_px[SLICES], sh_py[SLICES], sh_tx[SLICES], sh_ty[SLICES];
    __shared__ float sh_red[64];

    {
        const int sl   = tid >> 1;          // slice 0..127
        const int part = tid & 1;           // 0..1 (16 partials each)
        const int v4   = sl * (NB/4) + part * 4;    // float4 index

        float4 sv[4], xv[4], yv[4], mv4[4];
        int4   iv[4];
#pragma unroll
        for (int j = 0; j < 4; j++) {
            sv[j]  = __ldcg(((const float4*)g_s ) + v4 + j);
            xv[j]  = __ldcg(((const float4*)g_sx) + v4 + j);
            yv[j]  = __ldcg(((const float4*)g_sy) + v4 + j);
            mv4[j] = __ldcg(((const float4*)g_tv) + v4 + j);
            iv[j]  = __ldcg(((const int4*  )g_ti) + v4 + j);
        }

        float S = 0.f, SX = 0.f, SY = 0.f;
        float mv = -FLT_MAX; int mi = 0x7fffffff;
#pragma unroll
        for (int j = 0; j < 4; j++) {
            S  += ((sv[j].x + sv[j].y) + (sv[j].z + sv[j].w));
            SX += ((xv[j].x + xv[j].y) + (xv[j].z + xv[j].w));
            SY += ((yv[j].x + yv[j].y) + (yv[j].z + yv[j].w));
            // partials visited in increasing index order; strict '>' keeps
            // the first (smallest-index) maximum.
            if (mv4[j].x > mv) { mv = mv4[j].x; mi = iv[j].x; }
            if (mv4[j].y > mv) { mv = mv4[j].y; mi = iv[j].y; }
            if (mv4[j].z > mv) { mv = mv4[j].z; mi = iv[j].z; }
            if (mv4[j].w > mv) { mv = mv4[j].w; mi = iv[j].w; }
        }
        sS [tid] = S;  sSX[tid] = SX;  sSY[tid] = SY;
        sMV[tid] = mv; sMI[tid] = mi;
    }
    __syncthreads();

    if (tid < SLICES) {
        const int b = tid * 2;
        const float S  = sS [b] + sS [b+1];
        const float SX = sSX[b] + sSX[b+1];
        const float SY = sSY[b] + sSY[b+1];
        float mv = sMV[b]; int mi = sMI[b];
        if (sMV[b+1] > mv) { mv = sMV[b+1]; mi = sMI[b+1]; }

        const float inv = 1.0f / (S * 512.0f);
        sh_px[tid] = SX * inv;
        sh_py[tid] = SY * inv;
        sh_tx[tid] = (float)((mi & 511) + 1) * (1.0f / 512.0f);
        sh_ty[tid] = (float)((mi >> 9)  + 1) * (1.0f / 512.0f);
    }
    __syncthreads();

    if (tid < 64) {
        const int p0 = 2 * tid, p1 = 2 * tid + 1;
        const float px0 = sh_px[p0], py0 = sh_py[p0];
        const float px1 = sh_px[p1], py1 = sh_py[p1];
        const float tx0 = sh_tx[p0], ty0 = sh_ty[p0];
        const float tx1 = sh_tx[p1], ty1 = sh_ty[p1];

        const float dx0 = tx0 - px0, dy0 = ty0 - py0;
        const float dx1 = tx1 - px1, dy1 = ty1 - py1;
        const float ed  = sqrtf(dx0*dx0 + dy0*dy0) + sqrtf(dx1*dx1 + dy1*dy1);

        const float pvx = px0 - px1, pvy = py0 - py1;
        const float tvx = tx0 - tx1, tvy = ty0 - ty1;
        const float pd  = sqrtf(pvx*pvx + pvy*pvy);
        const float td  = sqrtf(tvx*tvx + tvy*tvy);
        const float dot = pvx*tvx + pvy*tvy;

        sh_red[tid] = ed + fabsf(pd - td) + (1.0f - cosf(dot / (pd * td)));
    }
    __syncthreads();

    if (tid < 32) {
        float a = sh_red[tid] + sh_red[tid + 32];
#pragma unroll
        for (int off = 16; off > 0; off >>= 1)
            a += __shfl_down_sync(0xffffffffu, a, off);
        if (tid == 0) {
            out[0] = a * (1.0f / 64.0f);
            g_count = 0;                    // reset for next graph replay
        }
    }
}

extern "C" void kernel_launch(void* const* d_in, const int* in_sizes, int n_in,
                              void* d_out, int out_size)
{
    const float4* inp = (const float4*)d_in[0];
    const float4* tgt = (const float4*)d_in[1];
    float* out = (float*)d_out;

    dsnt_fused<<<NBLOCKS, TPB>>>(inp, tgt, out);
}